// round 5
// baseline (speedup 1.0000x reference)
#include <cuda_runtime.h>
#include <math.h>

// Problem constants
#define BB 4
#define TT 2048
#define DD 1024
#define MR (BB * TT)          // 8192 flattened rows
#define ETA 0.1f
// GEMM tiling
#define BM 128
#define BN 128
#define BK 8
#define TM 8
#define TN 8
#define NTHREADS 256

// ------------------------------------------------------------------
// Device scratch (static allocation — no cudaMalloc allowed)
// ------------------------------------------------------------------
__device__ __align__(16) float g_u[2][MR * DD];      // u_q, u_k projections
__device__ __align__(16) float g_vst[2][MR * DD];    // LCA v state (q,k)
__device__ __align__(16) float g_a[2][2][MR * DD];   // [pingpong][q/k] sparse codes
__device__ __align__(16) float g_vv[MR * DD];        // value projection
__device__ __align__(16) float g_G[2][DD * DD];      // preprocessed Gq, Gk (symmetric)
__device__ float g_lam[2];
__device__ __align__(16) float g_scores[(size_t)BB * TT * TT];
__device__ __align__(16) float g_att[MR * DD];

enum { EPI_STORE = 0, EPI_SCALE = 1, EPI_QKV = 2, EPI_LCA = 3 };

__device__ __forceinline__ float softthr(float v, float lam) {
    float t = fabsf(v) - lam;
    return t > 0.f ? copysignf(t, v) : 0.f;
}

// ------------------------------------------------------------------
// Generic 128x128x8 SIMT GEMM core, double-buffered smem.
// C[m,n] = sum_k A[m,k] * (TRANSB ? B[n,k] : B[k,n])
// All dims assumed multiples of 128 (true for this problem).
// ------------------------------------------------------------------
template <bool TRANSB, int EPI>
__device__ __forceinline__ void gemm_core(
    const float* __restrict__ A, const float* __restrict__ Bmat,
    float* __restrict__ C, int lda, int ldb, int ldc,
    int kEnd, float scale, int zsel, int pout)
{
    __shared__ float As[2][BK][BM];
    __shared__ float Bs[2][BK][BN];

    const int tid = threadIdx.x;
    const int m0 = blockIdx.y * BM;
    const int n0 = blockIdx.x * BN;
    const int ty = tid >> 4;        // 0..15
    const int tx = tid & 15;        // 0..15

    float acc[TM][TN] = {};

    // A tile loader: 128 rows x 8 k, one float4 per thread (transposed store)
    const int arow = tid >> 1;            // 0..127
    const int acol = (tid & 1) << 2;      // 0 or 4
    // B tile loader (NN): 8 k-rows x 128 cols, one float4 per thread
    const int brow = tid >> 5;            // 0..7
    const int bcol = (tid & 31) << 2;     // 0..124

    const float* Ap = A + (size_t)(m0 + arow) * lda + acol;
    const float* Bp = TRANSB ? (Bmat + (size_t)(n0 + arow) * ldb + acol)
                             : (Bmat + (size_t)brow * ldb + n0 + bcol);

    const int nk = kEnd / BK;

    float4 av = *(const float4*)Ap;
    float4 bv = *(const float4*)Bp;

    As[0][acol + 0][arow] = av.x; As[0][acol + 1][arow] = av.y;
    As[0][acol + 2][arow] = av.z; As[0][acol + 3][arow] = av.w;
    if (TRANSB) {
        Bs[0][acol + 0][arow] = bv.x; Bs[0][acol + 1][arow] = bv.y;
        Bs[0][acol + 2][arow] = bv.z; Bs[0][acol + 3][arow] = bv.w;
    } else {
        *(float4*)&Bs[0][brow][bcol] = bv;
    }
    __syncthreads();

    int buf = 0;
    for (int kb = 0; kb < nk; ++kb) {
        if (kb + 1 < nk) {
            av = *(const float4*)(Ap + (size_t)(kb + 1) * BK);
            bv = TRANSB ? *(const float4*)(Bp + (size_t)(kb + 1) * BK)
                        : *(const float4*)(Bp + (size_t)(kb + 1) * BK * ldb);
        }
        #pragma unroll
        for (int kk = 0; kk < BK; ++kk) {
            float af[TM], bf[TN];
            #pragma unroll
            for (int i = 0; i < TM; i += 4) {
                float4 t = *(const float4*)&As[buf][kk][ty * TM + i];
                af[i] = t.x; af[i + 1] = t.y; af[i + 2] = t.z; af[i + 3] = t.w;
            }
            #pragma unroll
            for (int j = 0; j < TN; j += 4) {
                float4 t = *(const float4*)&Bs[buf][kk][tx * TN + j];
                bf[j] = t.x; bf[j + 1] = t.y; bf[j + 2] = t.z; bf[j + 3] = t.w;
            }
            #pragma unroll
            for (int i = 0; i < TM; ++i)
                #pragma unroll
                for (int j = 0; j < TN; ++j)
                    acc[i][j] = fmaf(af[i], bf[j], acc[i][j]);
        }
        if (kb + 1 < nk) {
            const int nb = buf ^ 1;
            As[nb][acol + 0][arow] = av.x; As[nb][acol + 1][arow] = av.y;
            As[nb][acol + 2][arow] = av.z; As[nb][acol + 3][arow] = av.w;
            if (TRANSB) {
                Bs[nb][acol + 0][arow] = bv.x; Bs[nb][acol + 1][arow] = bv.y;
                Bs[nb][acol + 2][arow] = bv.z; Bs[nb][acol + 3][arow] = bv.w;
            } else {
                *(float4*)&Bs[nb][brow][bcol] = bv;
            }
            __syncthreads();
            buf = nb;
        }
    }

    // ---------------- Epilogues ----------------
    if (EPI == EPI_STORE || EPI == EPI_SCALE) {
        #pragma unroll
        for (int i = 0; i < TM; ++i) {
            float* crow = C + (size_t)(m0 + ty * TM + i) * ldc + n0 + tx * TN;
            #pragma unroll
            for (int j = 0; j < TN; j += 4) {
                float4 o;
                o.x = acc[i][j + 0] * scale; o.y = acc[i][j + 1] * scale;
                o.z = acc[i][j + 2] * scale; o.w = acc[i][j + 3] * scale;
                *(float4*)&crow[j] = o;
            }
        }
    } else if (EPI == EPI_QKV) {
        // route columns of qkv into u_q / u_k / v (n0 aligned to 128 <= 1024)
        float* dst; int nbase;
        if (n0 < DD)            { dst = g_u[0]; nbase = n0; }
        else if (n0 < 2 * DD)   { dst = g_u[1]; nbase = n0 - DD; }
        else                    { dst = g_vv;   nbase = n0 - 2 * DD; }
        #pragma unroll
        for (int i = 0; i < TM; ++i) {
            float* crow = dst + (size_t)(m0 + ty * TM + i) * DD + nbase + tx * TN;
            #pragma unroll
            for (int j = 0; j < TN; j += 4) {
                float4 o;
                o.x = acc[i][j + 0]; o.y = acc[i][j + 1];
                o.z = acc[i][j + 2]; o.w = acc[i][j + 3];
                *(float4*)&crow[j] = o;
            }
        }
    } else { // EPI_LCA : v += eta*(u - v - aG);  a = soft(v, lam)
        const float lam = g_lam[zsel];
        float* vp = g_vst[zsel];
        const float* up = g_u[zsel];
        float* ap = g_a[pout][zsel];
        #pragma unroll
        for (int i = 0; i < TM; ++i) {
            const size_t base = (size_t)(m0 + ty * TM + i) * DD + n0 + tx * TN;
            #pragma unroll
            for (int j = 0; j < TN; j += 4) {
                float4 uu = *(const float4*)&up[base + j];
                float4 vv = *(const float4*)&vp[base + j];
                float4 vn, an;
                vn.x = vv.x + ETA * (uu.x - vv.x - acc[i][j + 0]);
                vn.y = vv.y + ETA * (uu.y - vv.y - acc[i][j + 1]);
                vn.z = vv.z + ETA * (uu.z - vv.z - acc[i][j + 2]);
                vn.w = vv.w + ETA * (uu.w - vv.w - acc[i][j + 3]);
                an.x = softthr(vn.x, lam); an.y = softthr(vn.y, lam);
                an.z = softthr(vn.z, lam); an.w = softthr(vn.w, lam);
                *(float4*)&vp[base + j] = vn;
                *(float4*)&ap[base + j] = an;
            }
        }
    }
}

// ------------------------------------------------------------------
// Kernels
// ------------------------------------------------------------------
__global__ void k_prep(const float* __restrict__ Gq, const float* __restrict__ Gk,
                       const float* __restrict__ llq, const float* __restrict__ llk) {
    const size_t gid = (size_t)blockIdx.x * NTHREADS + threadIdx.x;
    if (gid == 0) { g_lam[0] = expf(llq[0]); g_lam[1] = expf(llk[0]); }
    const int z = (int)(gid >> 20);              // D*D = 2^20
    const int rc = (int)(gid & (DD * DD - 1));
    const int r = rc >> 10, c = rc & (DD - 1);
    const float* Gr = z ? Gk : Gq;
    g_G[z][rc] = (r == c) ? 0.f : 0.5f * (Gr[rc] + Gr[(size_t)c * DD + r]);
}

__global__ void k_qkv(const float* __restrict__ x, const float* __restrict__ W) {
    gemm_core<true, EPI_QKV>(x, W, nullptr, DD, DD, 0, DD, 1.f, 0, 0);
}

// LCA iteration 1 (a=0, v=0): v = eta*u, a = soft(v)
__global__ void k_lca_init() {
    const int z = blockIdx.z;
    const float lam = g_lam[z];
    const size_t i = (size_t)blockIdx.x * NTHREADS + threadIdx.x;
    float4 u = ((const float4*)g_u[z])[i];
    float4 v, a;
    v.x = ETA * u.x; v.y = ETA * u.y; v.z = ETA * u.z; v.w = ETA * u.w;
    a.x = softthr(v.x, lam); a.y = softthr(v.y, lam);
    a.z = softthr(v.z, lam); a.w = softthr(v.w, lam);
    ((float4*)g_vst[z])[i] = v;
    ((float4*)g_a[0][z])[i] = a;
}

__global__ void k_lca_gemm(int pin) {
    const int z = blockIdx.z;
    gemm_core<true, EPI_LCA>(g_a[pin][z], g_G[z], nullptr,
                             DD, DD, 0, DD, 1.f, z, pin ^ 1);
}

__global__ void k_scores() {
    if (blockIdx.x > blockIdx.y) return;   // block fully above causal diagonal
    const int b = blockIdx.z;
    gemm_core<true, EPI_SCALE>(g_a[1][0] + (size_t)b * TT * DD,
                               g_a[1][1] + (size_t)b * TT * DD,
                               g_scores + (size_t)b * TT * TT,
                               DD, DD, TT, DD, 0.03125f /*1/sqrt(1024)*/, 0, 0);
}

__global__ void k_softmax() {
    const int i = blockIdx.x, b = blockIdx.y, tid = threadIdx.x;
    float* s = g_scores + ((size_t)b * TT + i) * TT;
    const int len = i + 1;
    __shared__ float red[NTHREADS];

    float mx = -3.4e38f;
    for (int j = tid; j < len; j += NTHREADS) mx = fmaxf(mx, s[j]);
    red[tid] = mx; __syncthreads();
    for (int st = NTHREADS / 2; st > 0; st >>= 1) {
        if (tid < st) red[tid] = fmaxf(red[tid], red[tid + st]);
        __syncthreads();
    }
    mx = red[0]; __syncthreads();

    float sum = 0.f;
    for (int j = tid; j < len; j += NTHREADS) {
        float e = __expf(s[j] - mx);
        s[j] = e;
        sum += e;
    }
    red[tid] = sum; __syncthreads();
    for (int st = NTHREADS / 2; st > 0; st >>= 1) {
        if (tid < st) red[tid] += red[tid + st];
        __syncthreads();
    }
    const float inv = 1.f / red[0];

    for (int j = tid; j < len; j += NTHREADS) s[j] *= inv;
    for (int j = len + tid; j < TT; j += NTHREADS) s[j] = 0.f;  // zero masked cols
}

__global__ void k_av() {
    const int b = blockIdx.z;
    const int kEnd = (blockIdx.y + 1) * BM;   // causal: p[i,j]=0 for j>i
    gemm_core<false, EPI_STORE>(g_scores + (size_t)b * TT * TT,
                                g_vv + (size_t)b * TT * DD,
                                g_att + (size_t)b * TT * DD,
                                TT, DD, DD, kEnd, 1.f, 0, 0);
}

__global__ void k_out(const float* __restrict__ W, float* __restrict__ out) {
    gemm_core<true, EPI_STORE>(g_att, W, out, DD, DD, DD, DD, 1.f, 0, 0);
}

// ------------------------------------------------------------------
// Launch (graph-capturable: kernels only, default stream)
// ------------------------------------------------------------------
extern "C" void kernel_launch(void* const* d_in, const int* in_sizes, int n_in,
                              void* d_out, int out_size) {
    const float* x    = (const float*)d_in[0];  // [4,2048,1024]
    const float* Wqkv = (const float*)d_in[1];  // [3072,1024]
    const float* Wout = (const float*)d_in[2];  // [1024,1024]
    const float* Gq   = (const float*)d_in[3];  // [1024,1024]
    const float* llq  = (const float*)d_in[4];  // scalar
    const float* Gk   = (const float*)d_in[5];  // [1024,1024]
    const float* llk  = (const float*)d_in[6];  // scalar
    float* out = (float*)d_out;                 // [4,2048,1024]

    // G symmetrize + zero diag, lam = exp(log_lam)
    k_prep<<<2 * DD * DD / NTHREADS, NTHREADS>>>(Gq, Gk, llq, llk);

    // qkv projection, columns routed to u_q / u_k / v
    k_qkv<<<dim3(3 * DD / BN, MR / BM), NTHREADS>>>(x, Wqkv);

    // LCA iteration 1 (elementwise), then 9 GEMM iterations for q and k (z-dim)
    k_lca_init<<<dim3(MR * DD / 4 / NTHREADS, 1, 2), NTHREADS>>>();
    for (int it = 0; it < 9; ++it)
        k_lca_gemm<<<dim3(DD / BN, MR / BM, 2), NTHREADS>>>(it & 1);

    // attention
    k_scores<<<dim3(TT / BN, TT / BM, BB), NTHREADS>>>();
    k_softmax<<<dim3(TT, BB), NTHREADS>>>();
    k_av<<<dim3(DD / BN, TT / BM, BB), NTHREADS>>>();

    // output projection
    k_out<<<dim3(DD / BN, MR / BM), NTHREADS>>>(Wout, out);
}

// round 9
// speedup vs baseline: 1.0003x; 1.0003x over previous
#include <cuda_runtime.h>
#include <math.h>

// Problem constants
#define BB 4
#define TT 2048
#define DD 1024
#define MR (BB * TT)          // 8192 flattened rows
#define ETA 0.1f
// GEMM tiling
#define BM 128
#define BN 128
#define BK 8
#define TM 8
#define TN 8
#define NTHREADS 256

// ------------------------------------------------------------------
// Device scratch (static allocation — no cudaMalloc allowed)
// ------------------------------------------------------------------
__device__ __align__(16) float g_u[2][MR * DD];      // u_q, u_k projections
__device__ __align__(16) float g_vst[2][MR * DD];    // LCA v state (q,k)
__device__ __align__(16) float g_a[2][2][MR * DD];   // [pingpong][q/k] sparse codes
__device__ __align__(16) float g_vv[MR * DD];        // value projection
__device__ __align__(16) float g_G[2][DD * DD];      // preprocessed Gq, Gk (symmetric)
__device__ float g_lam[2];
__device__ __align__(16) float g_scores[(size_t)BB * TT * TT];
__device__ __align__(16) float g_att[MR * DD];

enum { EPI_STORE = 0, EPI_SCALE = 1, EPI_QKV = 2, EPI_LCA = 3 };

__device__ __forceinline__ float softthr(float v, float lam) {
    float t = fabsf(v) - lam;
    return t > 0.f ? copysignf(t, v) : 0.f;
}

// ------------------------------------------------------------------
// Generic 128x128x8 SIMT GEMM core, double-buffered smem.
// C[m,n] = sum_k A[m,k] * (TRANSB ? B[n,k] : B[k,n])
// All dims assumed multiples of 128 (true for this problem).
// ------------------------------------------------------------------
template <bool TRANSB, int EPI>
__device__ __forceinline__ void gemm_core(
    const float* __restrict__ A, const float* __restrict__ Bmat,
    float* __restrict__ C, int lda, int ldb, int ldc,
    int kEnd, float scale, int zsel, int pout)
{
    __shared__ float As[2][BK][BM];
    __shared__ float Bs[2][BK][BN];

    const int tid = threadIdx.x;
    const int m0 = blockIdx.y * BM;
    const int n0 = blockIdx.x * BN;
    const int ty = tid >> 4;        // 0..15
    const int tx = tid & 15;        // 0..15

    float acc[TM][TN] = {};

    // A tile loader: 128 rows x 8 k, one float4 per thread (transposed store)
    const int arow = tid >> 1;            // 0..127
    const int acol = (tid & 1) << 2;      // 0 or 4
    // B tile loader (NN): 8 k-rows x 128 cols, one float4 per thread
    const int brow = tid >> 5;            // 0..7
    const int bcol = (tid & 31) << 2;     // 0..124

    const float* Ap = A + (size_t)(m0 + arow) * lda + acol;
    const float* Bp = TRANSB ? (Bmat + (size_t)(n0 + arow) * ldb + acol)
                             : (Bmat + (size_t)brow * ldb + n0 + bcol);

    const int nk = kEnd / BK;

    float4 av = *(const float4*)Ap;
    float4 bv = *(const float4*)Bp;

    As[0][acol + 0][arow] = av.x; As[0][acol + 1][arow] = av.y;
    As[0][acol + 2][arow] = av.z; As[0][acol + 3][arow] = av.w;
    if (TRANSB) {
        Bs[0][acol + 0][arow] = bv.x; Bs[0][acol + 1][arow] = bv.y;
        Bs[0][acol + 2][arow] = bv.z; Bs[0][acol + 3][arow] = bv.w;
    } else {
        *(float4*)&Bs[0][brow][bcol] = bv;
    }
    __syncthreads();

    int buf = 0;
    for (int kb = 0; kb < nk; ++kb) {
        if (kb + 1 < nk) {
            av = *(const float4*)(Ap + (size_t)(kb + 1) * BK);
            bv = TRANSB ? *(const float4*)(Bp + (size_t)(kb + 1) * BK)
                        : *(const float4*)(Bp + (size_t)(kb + 1) * BK * ldb);
        }
        #pragma unroll
        for (int kk = 0; kk < BK; ++kk) {
            float af[TM], bf[TN];
            #pragma unroll
            for (int i = 0; i < TM; i += 4) {
                float4 t = *(const float4*)&As[buf][kk][ty * TM + i];
                af[i] = t.x; af[i + 1] = t.y; af[i + 2] = t.z; af[i + 3] = t.w;
            }
            #pragma unroll
            for (int j = 0; j < TN; j += 4) {
                float4 t = *(const float4*)&Bs[buf][kk][tx * TN + j];
                bf[j] = t.x; bf[j + 1] = t.y; bf[j + 2] = t.z; bf[j + 3] = t.w;
            }
            #pragma unroll
            for (int i = 0; i < TM; ++i)
                #pragma unroll
                for (int j = 0; j < TN; ++j)
                    acc[i][j] = fmaf(af[i], bf[j], acc[i][j]);
        }
        if (kb + 1 < nk) {
            const int nb = buf ^ 1;
            As[nb][acol + 0][arow] = av.x; As[nb][acol + 1][arow] = av.y;
            As[nb][acol + 2][arow] = av.z; As[nb][acol + 3][arow] = av.w;
            if (TRANSB) {
                Bs[nb][acol + 0][arow] = bv.x; Bs[nb][acol + 1][arow] = bv.y;
                Bs[nb][acol + 2][arow] = bv.z; Bs[nb][acol + 3][arow] = bv.w;
            } else {
                *(float4*)&Bs[nb][brow][bcol] = bv;
            }
            __syncthreads();
            buf = nb;
        }
    }

    // ---------------- Epilogues ----------------
    if (EPI == EPI_STORE || EPI == EPI_SCALE) {
        #pragma unroll
        for (int i = 0; i < TM; ++i) {
            float* crow = C + (size_t)(m0 + ty * TM + i) * ldc + n0 + tx * TN;
            #pragma unroll
            for (int j = 0; j < TN; j += 4) {
                float4 o;
                o.x = acc[i][j + 0] * scale; o.y = acc[i][j + 1] * scale;
                o.z = acc[i][j + 2] * scale; o.w = acc[i][j + 3] * scale;
                *(float4*)&crow[j] = o;
            }
        }
    } else if (EPI == EPI_QKV) {
        // route columns of qkv into u_q / u_k / v (n0 aligned to 128 <= 1024)
        float* dst; int nbase;
        if (n0 < DD)            { dst = g_u[0]; nbase = n0; }
        else if (n0 < 2 * DD)   { dst = g_u[1]; nbase = n0 - DD; }
        else                    { dst = g_vv;   nbase = n0 - 2 * DD; }
        #pragma unroll
        for (int i = 0; i < TM; ++i) {
            float* crow = dst + (size_t)(m0 + ty * TM + i) * DD + nbase + tx * TN;
            #pragma unroll
            for (int j = 0; j < TN; j += 4) {
                float4 o;
                o.x = acc[i][j + 0]; o.y = acc[i][j + 1];
                o.z = acc[i][j + 2]; o.w = acc[i][j + 3];
                *(float4*)&crow[j] = o;
            }
        }
    } else { // EPI_LCA : v += eta*(u - v - aG);  a = soft(v, lam)
        const float lam = g_lam[zsel];
        float* vp = g_vst[zsel];
        const float* up = g_u[zsel];
        float* ap = g_a[pout][zsel];
        #pragma unroll
        for (int i = 0; i < TM; ++i) {
            const size_t base = (size_t)(m0 + ty * TM + i) * DD + n0 + tx * TN;
            #pragma unroll
            for (int j = 0; j < TN; j += 4) {
                float4 uu = *(const float4*)&up[base + j];
                float4 vv = *(const float4*)&vp[base + j];
                float4 vn, an;
                vn.x = vv.x + ETA * (uu.x - vv.x - acc[i][j + 0]);
                vn.y = vv.y + ETA * (uu.y - vv.y - acc[i][j + 1]);
                vn.z = vv.z + ETA * (uu.z - vv.z - acc[i][j + 2]);
                vn.w = vv.w + ETA * (uu.w - vv.w - acc[i][j + 3]);
                an.x = softthr(vn.x, lam); an.y = softthr(vn.y, lam);
                an.z = softthr(vn.z, lam); an.w = softthr(vn.w, lam);
                *(float4*)&vp[base + j] = vn;
                *(float4*)&ap[base + j] = an;
            }
        }
    }
}

// ------------------------------------------------------------------
// Kernels
// ------------------------------------------------------------------
__global__ void k_prep(const float* __restrict__ Gq, const float* __restrict__ Gk,
                       const float* __restrict__ llq, const float* __restrict__ llk) {
    const size_t gid = (size_t)blockIdx.x * NTHREADS + threadIdx.x;
    if (gid == 0) { g_lam[0] = expf(llq[0]); g_lam[1] = expf(llk[0]); }
    const int z = (int)(gid >> 20);              // D*D = 2^20
    const int rc = (int)(gid & (DD * DD - 1));
    const int r = rc >> 10, c = rc & (DD - 1);
    const float* Gr = z ? Gk : Gq;
    g_G[z][rc] = (r == c) ? 0.f : 0.5f * (Gr[rc] + Gr[(size_t)c * DD + r]);
}

__global__ void k_qkv(const float* __restrict__ x, const float* __restrict__ W) {
    gemm_core<true, EPI_QKV>(x, W, nullptr, DD, DD, 0, DD, 1.f, 0, 0);
}

// LCA iteration 1 (a=0, v=0): v = eta*u, a = soft(v)
__global__ void k_lca_init() {
    const int z = blockIdx.z;
    const float lam = g_lam[z];
    const size_t i = (size_t)blockIdx.x * NTHREADS + threadIdx.x;
    float4 u = ((const float4*)g_u[z])[i];
    float4 v, a;
    v.x = ETA * u.x; v.y = ETA * u.y; v.z = ETA * u.z; v.w = ETA * u.w;
    a.x = softthr(v.x, lam); a.y = softthr(v.y, lam);
    a.z = softthr(v.z, lam); a.w = softthr(v.w, lam);
    ((float4*)g_vst[z])[i] = v;
    ((float4*)g_a[0][z])[i] = a;
}

__global__ void k_lca_gemm(int pin) {
    const int z = blockIdx.z;
    gemm_core<true, EPI_LCA>(g_a[pin][z], g_G[z], nullptr,
                             DD, DD, 0, DD, 1.f, z, pin ^ 1);
}

__global__ void k_scores() {
    if (blockIdx.x > blockIdx.y) return;   // block fully above causal diagonal
    const int b = blockIdx.z;
    gemm_core<true, EPI_SCALE>(g_a[1][0] + (size_t)b * TT * DD,
                               g_a[1][1] + (size_t)b * TT * DD,
                               g_scores + (size_t)b * TT * TT,
                               DD, DD, TT, DD, 0.03125f /*1/sqrt(1024)*/, 0, 0);
}

__global__ void k_softmax() {
    const int i = blockIdx.x, b = blockIdx.y, tid = threadIdx.x;
    float* s = g_scores + ((size_t)b * TT + i) * TT;
    const int len = i + 1;
    __shared__ float red[NTHREADS];

    float mx = -3.4e38f;
    for (int j = tid; j < len; j += NTHREADS) mx = fmaxf(mx, s[j]);
    red[tid] = mx; __syncthreads();
    for (int st = NTHREADS / 2; st > 0; st >>= 1) {
        if (tid < st) red[tid] = fmaxf(red[tid], red[tid + st]);
        __syncthreads();
    }
    mx = red[0]; __syncthreads();

    float sum = 0.f;
    for (int j = tid; j < len; j += NTHREADS) {
        float e = __expf(s[j] - mx);
        s[j] = e;
        sum += e;
    }
    red[tid] = sum; __syncthreads();
    for (int st = NTHREADS / 2; st > 0; st >>= 1) {
        if (tid < st) red[tid] += red[tid + st];
        __syncthreads();
    }
    const float inv = 1.f / red[0];

    for (int j = tid; j < len; j += NTHREADS) s[j] *= inv;
    for (int j = len + tid; j < TT; j += NTHREADS) s[j] = 0.f;  // zero masked cols
}

__global__ void k_av() {
    const int b = blockIdx.z;
    const int kEnd = (blockIdx.y + 1) * BM;   // causal: p[i,j]=0 for j>i
    gemm_core<false, EPI_STORE>(g_scores + (size_t)b * TT * TT,
                                g_vv + (size_t)b * TT * DD,
                                g_att + (size_t)b * TT * DD,
                                TT, DD, DD, kEnd, 1.f, 0, 0);
}

__global__ void k_out(const float* __restrict__ W, float* __restrict__ out) {
    gemm_core<true, EPI_STORE>(g_att, W, out, DD, DD, DD, DD, 1.f, 0, 0);
}

// ------------------------------------------------------------------
// Launch (graph-capturable: kernels only, default stream)
// ------------------------------------------------------------------
extern "C" void kernel_launch(void* const* d_in, const int* in_sizes, int n_in,
                              void* d_out, int out_size) {
    const float* x    = (const float*)d_in[0];  // [4,2048,1024]
    const float* Wqkv = (const float*)d_in[1];  // [3072,1024]
    const float* Wout = (const float*)d_in[2];  // [1024,1024]
    const float* Gq   = (const float*)d_in[3];  // [1024,1024]
    const float* llq  = (const float*)d_in[4];  // scalar
    const float* Gk   = (const float*)d_in[5];  // [1024,1024]
    const float* llk  = (const float*)d_in[6];  // scalar
    float* out = (float*)d_out;                 // [4,2048,1024]

    // G symmetrize + zero diag, lam = exp(log_lam)
    k_prep<<<2 * DD * DD / NTHREADS, NTHREADS>>>(Gq, Gk, llq, llk);

    // qkv projection, columns routed to u_q / u_k / v
    k_qkv<<<dim3(3 * DD / BN, MR / BM), NTHREADS>>>(x, Wqkv);

    // LCA iteration 1 (elementwise), then 9 GEMM iterations for q and k (z-dim)
    k_lca_init<<<dim3(MR * DD / 4 / NTHREADS, 1, 2), NTHREADS>>>();
    for (int it = 0; it < 9; ++it)
        k_lca_gemm<<<dim3(DD / BN, MR / BM, 2), NTHREADS>>>(it & 1);

    // attention
    k_scores<<<dim3(TT / BN, TT / BM, BB), NTHREADS>>>();
    k_softmax<<<dim3(TT, BB), NTHREADS>>>();
    k_av<<<dim3(DD / BN, TT / BM, BB), NTHREADS>>>();

    // output projection
    k_out<<<dim3(DD / BN, MR / BM), NTHREADS>>>(Wout, out);
}

// round 13
// speedup vs baseline: 1.0009x; 1.0006x over previous
#include <cuda_runtime.h>
#include <math.h>

// Problem constants
#define BB 4
#define TT 2048
#define DD 1024
#define MR (BB * TT)          // 8192 flattened rows
#define ETA 0.1f
// GEMM tiling
#define BM 128
#define BN 128
#define BK 8
#define TM 8
#define TN 8
#define NTHREADS 256

// ------------------------------------------------------------------
// Device scratch (static allocation — no cudaMalloc allowed)
// ------------------------------------------------------------------
__device__ __align__(16) float g_u[2][MR * DD];      // u_q, u_k projections
__device__ __align__(16) float g_vst[2][MR * DD];    // LCA v state (q,k)
__device__ __align__(16) float g_a[2][2][MR * DD];   // [pingpong][q/k] sparse codes
__device__ __align__(16) float g_vv[MR * DD];        // value projection
__device__ __align__(16) float g_G[2][DD * DD];      // preprocessed Gq, Gk (symmetric)
__device__ float g_lam[2];
__device__ __align__(16) float g_scores[(size_t)BB * TT * TT];
__device__ __align__(16) float g_att[MR * DD];

enum { EPI_STORE = 0, EPI_SCALE = 1, EPI_QKV = 2, EPI_LCA = 3 };

__device__ __forceinline__ float softthr(float v, float lam) {
    float t = fabsf(v) - lam;
    return t > 0.f ? copysignf(t, v) : 0.f;
}

// ------------------------------------------------------------------
// Generic 128x128x8 SIMT GEMM core, double-buffered smem.
// C[m,n] = sum_k A[m,k] * (TRANSB ? B[n,k] : B[k,n])
// All dims assumed multiples of 128 (true for this problem).
// ------------------------------------------------------------------
template <bool TRANSB, int EPI>
__device__ __forceinline__ void gemm_core(
    const float* __restrict__ A, const float* __restrict__ Bmat,
    float* __restrict__ C, int lda, int ldb, int ldc,
    int kEnd, float scale, int zsel, int pout)
{
    __shared__ float As[2][BK][BM];
    __shared__ float Bs[2][BK][BN];

    const int tid = threadIdx.x;
    const int m0 = blockIdx.y * BM;
    const int n0 = blockIdx.x * BN;
    const int ty = tid >> 4;        // 0..15
    const int tx = tid & 15;        // 0..15

    float acc[TM][TN] = {};

    // A tile loader: 128 rows x 8 k, one float4 per thread (transposed store)
    const int arow = tid >> 1;            // 0..127
    const int acol = (tid & 1) << 2;      // 0 or 4
    // B tile loader (NN): 8 k-rows x 128 cols, one float4 per thread
    const int brow = tid >> 5;            // 0..7
    const int bcol = (tid & 31) << 2;     // 0..124

    const float* Ap = A + (size_t)(m0 + arow) * lda + acol;
    const float* Bp = TRANSB ? (Bmat + (size_t)(n0 + arow) * ldb + acol)
                             : (Bmat + (size_t)brow * ldb + n0 + bcol);

    const int nk = kEnd / BK;

    float4 av = *(const float4*)Ap;
    float4 bv = *(const float4*)Bp;

    As[0][acol + 0][arow] = av.x; As[0][acol + 1][arow] = av.y;
    As[0][acol + 2][arow] = av.z; As[0][acol + 3][arow] = av.w;
    if (TRANSB) {
        Bs[0][acol + 0][arow] = bv.x; Bs[0][acol + 1][arow] = bv.y;
        Bs[0][acol + 2][arow] = bv.z; Bs[0][acol + 3][arow] = bv.w;
    } else {
        *(float4*)&Bs[0][brow][bcol] = bv;
    }
    __syncthreads();

    int buf = 0;
    for (int kb = 0; kb < nk; ++kb) {
        if (kb + 1 < nk) {
            av = *(const float4*)(Ap + (size_t)(kb + 1) * BK);
            bv = TRANSB ? *(const float4*)(Bp + (size_t)(kb + 1) * BK)
                        : *(const float4*)(Bp + (size_t)(kb + 1) * BK * ldb);
        }
        #pragma unroll
        for (int kk = 0; kk < BK; ++kk) {
            float af[TM], bf[TN];
            #pragma unroll
            for (int i = 0; i < TM; i += 4) {
                float4 t = *(const float4*)&As[buf][kk][ty * TM + i];
                af[i] = t.x; af[i + 1] = t.y; af[i + 2] = t.z; af[i + 3] = t.w;
            }
            #pragma unroll
            for (int j = 0; j < TN; j += 4) {
                float4 t = *(const float4*)&Bs[buf][kk][tx * TN + j];
                bf[j] = t.x; bf[j + 1] = t.y; bf[j + 2] = t.z; bf[j + 3] = t.w;
            }
            #pragma unroll
            for (int i = 0; i < TM; ++i)
                #pragma unroll
                for (int j = 0; j < TN; ++j)
                    acc[i][j] = fmaf(af[i], bf[j], acc[i][j]);
        }
        if (kb + 1 < nk) {
            const int nb = buf ^ 1;
            As[nb][acol + 0][arow] = av.x; As[nb][acol + 1][arow] = av.y;
            As[nb][acol + 2][arow] = av.z; As[nb][acol + 3][arow] = av.w;
            if (TRANSB) {
                Bs[nb][acol + 0][arow] = bv.x; Bs[nb][acol + 1][arow] = bv.y;
                Bs[nb][acol + 2][arow] = bv.z; Bs[nb][acol + 3][arow] = bv.w;
            } else {
                *(float4*)&Bs[nb][brow][bcol] = bv;
            }
            __syncthreads();
            buf = nb;
        }
    }

    // ---------------- Epilogues ----------------
    if (EPI == EPI_STORE || EPI == EPI_SCALE) {
        #pragma unroll
        for (int i = 0; i < TM; ++i) {
            float* crow = C + (size_t)(m0 + ty * TM + i) * ldc + n0 + tx * TN;
            #pragma unroll
            for (int j = 0; j < TN; j += 4) {
                float4 o;
                o.x = acc[i][j + 0] * scale; o.y = acc[i][j + 1] * scale;
                o.z = acc[i][j + 2] * scale; o.w = acc[i][j + 3] * scale;
                *(float4*)&crow[j] = o;
            }
        }
    } else if (EPI == EPI_QKV) {
        // route columns of qkv into u_q / u_k / v (n0 aligned to 128 <= 1024)
        float* dst; int nbase;
        if (n0 < DD)            { dst = g_u[0]; nbase = n0; }
        else if (n0 < 2 * DD)   { dst = g_u[1]; nbase = n0 - DD; }
        else                    { dst = g_vv;   nbase = n0 - 2 * DD; }
        #pragma unroll
        for (int i = 0; i < TM; ++i) {
            float* crow = dst + (size_t)(m0 + ty * TM + i) * DD + nbase + tx * TN;
            #pragma unroll
            for (int j = 0; j < TN; j += 4) {
                float4 o;
                o.x = acc[i][j + 0]; o.y = acc[i][j + 1];
                o.z = acc[i][j + 2]; o.w = acc[i][j + 3];
                *(float4*)&crow[j] = o;
            }
        }
    } else { // EPI_LCA : v += eta*(u - v - aG);  a = soft(v, lam)
        const float lam = g_lam[zsel];
        float* vp = g_vst[zsel];
        const float* up = g_u[zsel];
        float* ap = g_a[pout][zsel];
        #pragma unroll
        for (int i = 0; i < TM; ++i) {
            const size_t base = (size_t)(m0 + ty * TM + i) * DD + n0 + tx * TN;
            #pragma unroll
            for (int j = 0; j < TN; j += 4) {
                float4 uu = *(const float4*)&up[base + j];
                float4 vv = *(const float4*)&vp[base + j];
                float4 vn, an;
                vn.x = vv.x + ETA * (uu.x - vv.x - acc[i][j + 0]);
                vn.y = vv.y + ETA * (uu.y - vv.y - acc[i][j + 1]);
                vn.z = vv.z + ETA * (uu.z - vv.z - acc[i][j + 2]);
                vn.w = vv.w + ETA * (uu.w - vv.w - acc[i][j + 3]);
                an.x = softthr(vn.x, lam); an.y = softthr(vn.y, lam);
                an.z = softthr(vn.z, lam); an.w = softthr(vn.w, lam);
                *(float4*)&vp[base + j] = vn;
                *(float4*)&ap[base + j] = an;
            }
        }
    }
}

// ------------------------------------------------------------------
// Kernels
// ------------------------------------------------------------------
__global__ void k_prep(const float* __restrict__ Gq, const float* __restrict__ Gk,
                       const float* __restrict__ llq, const float* __restrict__ llk) {
    const size_t gid = (size_t)blockIdx.x * NTHREADS + threadIdx.x;
    if (gid == 0) { g_lam[0] = expf(llq[0]); g_lam[1] = expf(llk[0]); }
    const int z = (int)(gid >> 20);              // D*D = 2^20
    const int rc = (int)(gid & (DD * DD - 1));
    const int r = rc >> 10, c = rc & (DD - 1);
    const float* Gr = z ? Gk : Gq;
    g_G[z][rc] = (r == c) ? 0.f : 0.5f * (Gr[rc] + Gr[(size_t)c * DD + r]);
}

__global__ void k_qkv(const float* __restrict__ x, const float* __restrict__ W) {
    gemm_core<true, EPI_QKV>(x, W, nullptr, DD, DD, 0, DD, 1.f, 0, 0);
}

// LCA iteration 1 (a=0, v=0): v = eta*u, a = soft(v)
__global__ void k_lca_init() {
    const int z = blockIdx.z;
    const float lam = g_lam[z];
    const size_t i = (size_t)blockIdx.x * NTHREADS + threadIdx.x;
    float4 u = ((const float4*)g_u[z])[i];
    float4 v, a;
    v.x = ETA * u.x; v.y = ETA * u.y; v.z = ETA * u.z; v.w = ETA * u.w;
    a.x = softthr(v.x, lam); a.y = softthr(v.y, lam);
    a.z = softthr(v.z, lam); a.w = softthr(v.w, lam);
    ((float4*)g_vst[z])[i] = v;
    ((float4*)g_a[0][z])[i] = a;
}

__global__ void k_lca_gemm(int pin) {
    const int z = blockIdx.z;
    gemm_core<true, EPI_LCA>(g_a[pin][z], g_G[z], nullptr,
                             DD, DD, 0, DD, 1.f, z, pin ^ 1);
}

__global__ void k_scores() {
    if (blockIdx.x > blockIdx.y) return;   // block fully above causal diagonal
    const int b = blockIdx.z;
    gemm_core<true, EPI_SCALE>(g_a[1][0] + (size_t)b * TT * DD,
                               g_a[1][1] + (size_t)b * TT * DD,
                               g_scores + (size_t)b * TT * TT,
                               DD, DD, TT, DD, 0.03125f /*1/sqrt(1024)*/, 0, 0);
}

__global__ void k_softmax() {
    const int i = blockIdx.x, b = blockIdx.y, tid = threadIdx.x;
    float* s = g_scores + ((size_t)b * TT + i) * TT;
    const int len = i + 1;
    __shared__ float red[NTHREADS];

    float mx = -3.4e38f;
    for (int j = tid; j < len; j += NTHREADS) mx = fmaxf(mx, s[j]);
    red[tid] = mx; __syncthreads();
    for (int st = NTHREADS / 2; st > 0; st >>= 1) {
        if (tid < st) red[tid] = fmaxf(red[tid], red[tid + st]);
        __syncthreads();
    }
    mx = red[0]; __syncthreads();

    float sum = 0.f;
    for (int j = tid; j < len; j += NTHREADS) {
        float e = __expf(s[j] - mx);
        s[j] = e;
        sum += e;
    }
    red[tid] = sum; __syncthreads();
    for (int st = NTHREADS / 2; st > 0; st >>= 1) {
        if (tid < st) red[tid] += red[tid + st];
        __syncthreads();
    }
    const float inv = 1.f / red[0];

    for (int j = tid; j < len; j += NTHREADS) s[j] *= inv;
    for (int j = len + tid; j < TT; j += NTHREADS) s[j] = 0.f;  // zero masked cols
}

__global__ void k_av() {
    const int b = blockIdx.z;
    const int kEnd = (blockIdx.y + 1) * BM;   // causal: p[i,j]=0 for j>i
    gemm_core<false, EPI_STORE>(g_scores + (size_t)b * TT * TT,
                                g_vv + (size_t)b * TT * DD,
                                g_att + (size_t)b * TT * DD,
                                TT, DD, DD, kEnd, 1.f, 0, 0);
}

__global__ void k_out(const float* __restrict__ W, float* __restrict__ out) {
    gemm_core<true, EPI_STORE>(g_att, W, out, DD, DD, DD, DD, 1.f, 0, 0);
}

// ------------------------------------------------------------------
// Launch (graph-capturable: kernels only, default stream)
// ------------------------------------------------------------------
extern "C" void kernel_launch(void* const* d_in, const int* in_sizes, int n_in,
                              void* d_out, int out_size) {
    const float* x    = (const float*)d_in[0];  // [4,2048,1024]
    const float* Wqkv = (const float*)d_in[1];  // [3072,1024]
    const float* Wout = (const float*)d_in[2];  // [1024,1024]
    const float* Gq   = (const float*)d_in[3];  // [1024,1024]
    const float* llq  = (const float*)d_in[4];  // scalar
    const float* Gk   = (const float*)d_in[5];  // [1024,1024]
    const float* llk  = (const float*)d_in[6];  // scalar
    float* out = (float*)d_out;                 // [4,2048,1024]

    // G symmetrize + zero diag, lam = exp(log_lam)
    k_prep<<<2 * DD * DD / NTHREADS, NTHREADS>>>(Gq, Gk, llq, llk);

    // qkv projection, columns routed to u_q / u_k / v
    k_qkv<<<dim3(3 * DD / BN, MR / BM), NTHREADS>>>(x, Wqkv);

    // LCA iteration 1 (elementwise), then 9 GEMM iterations for q and k (z-dim)
    k_lca_init<<<dim3(MR * DD / 4 / NTHREADS, 1, 2), NTHREADS>>>();
    for (int it = 0; it < 9; ++it)
        k_lca_gemm<<<dim3(DD / BN, MR / BM, 2), NTHREADS>>>(it & 1);

    // attention
    k_scores<<<dim3(TT / BN, TT / BM, BB), NTHREADS>>>();
    k_softmax<<<dim3(TT, BB), NTHREADS>>>();
    k_av<<<dim3(DD / BN, TT / BM, BB), NTHREADS>>>();

    // output projection
    k_out<<<dim3(DD / BN, MR / BM), NTHREADS>>>(Wout, out);
}

// round 14
// speedup vs baseline: 1.0010x; 1.0001x over previous
#include <cuda_runtime.h>
#include <math.h>

// Problem constants
#define BB 4
#define TT 2048
#define DD 1024
#define MR (BB * TT)          // 8192 flattened rows
#define ETA 0.1f
// GEMM tiling
#define BM 128
#define BN 128
#define BK 8
#define TM 8
#define TN 8
#define NTHREADS 256

// ------------------------------------------------------------------
// Device scratch (static allocation — no cudaMalloc allowed)
// ------------------------------------------------------------------
__device__ __align__(16) float g_u[2][MR * DD];      // u_q, u_k projections
__device__ __align__(16) float g_vst[2][MR * DD];    // LCA v state (q,k)
__device__ __align__(16) float g_a[2][2][MR * DD];   // [pingpong][q/k] sparse codes
__device__ __align__(16) float g_vv[MR * DD];        // value projection
__device__ __align__(16) float g_G[2][DD * DD];      // preprocessed Gq, Gk (symmetric)
__device__ float g_lam[2];
__device__ __align__(16) float g_scores[(size_t)BB * TT * TT];
__device__ __align__(16) float g_att[MR * DD];

enum { EPI_STORE = 0, EPI_SCALE = 1, EPI_QKV = 2, EPI_LCA = 3 };

__device__ __forceinline__ float softthr(float v, float lam) {
    float t = fabsf(v) - lam;
    return t > 0.f ? copysignf(t, v) : 0.f;
}

// ------------------------------------------------------------------
// Generic 128x128x8 SIMT GEMM core, double-buffered smem.
// C[m,n] = sum_k A[m,k] * (TRANSB ? B[n,k] : B[k,n])
// All dims assumed multiples of 128 (true for this problem).
// ------------------------------------------------------------------
template <bool TRANSB, int EPI>
__device__ __forceinline__ void gemm_core(
    const float* __restrict__ A, const float* __restrict__ Bmat,
    float* __restrict__ C, int lda, int ldb, int ldc,
    int kEnd, float scale, int zsel, int pout)
{
    __shared__ float As[2][BK][BM];
    __shared__ float Bs[2][BK][BN];

    const int tid = threadIdx.x;
    const int m0 = blockIdx.y * BM;
    const int n0 = blockIdx.x * BN;
    const int ty = tid >> 4;        // 0..15
    const int tx = tid & 15;        // 0..15

    float acc[TM][TN] = {};

    // A tile loader: 128 rows x 8 k, one float4 per thread (transposed store)
    const int arow = tid >> 1;            // 0..127
    const int acol = (tid & 1) << 2;      // 0 or 4
    // B tile loader (NN): 8 k-rows x 128 cols, one float4 per thread
    const int brow = tid >> 5;            // 0..7
    const int bcol = (tid & 31) << 2;     // 0..124

    const float* Ap = A + (size_t)(m0 + arow) * lda + acol;
    const float* Bp = TRANSB ? (Bmat + (size_t)(n0 + arow) * ldb + acol)
                             : (Bmat + (size_t)brow * ldb + n0 + bcol);

    const int nk = kEnd / BK;

    float4 av = *(const float4*)Ap;
    float4 bv = *(const float4*)Bp;

    As[0][acol + 0][arow] = av.x; As[0][acol + 1][arow] = av.y;
    As[0][acol + 2][arow] = av.z; As[0][acol + 3][arow] = av.w;
    if (TRANSB) {
        Bs[0][acol + 0][arow] = bv.x; Bs[0][acol + 1][arow] = bv.y;
        Bs[0][acol + 2][arow] = bv.z; Bs[0][acol + 3][arow] = bv.w;
    } else {
        *(float4*)&Bs[0][brow][bcol] = bv;
    }
    __syncthreads();

    int buf = 0;
    for (int kb = 0; kb < nk; ++kb) {
        if (kb + 1 < nk) {
            av = *(const float4*)(Ap + (size_t)(kb + 1) * BK);
            bv = TRANSB ? *(const float4*)(Bp + (size_t)(kb + 1) * BK)
                        : *(const float4*)(Bp + (size_t)(kb + 1) * BK * ldb);
        }
        #pragma unroll
        for (int kk = 0; kk < BK; ++kk) {
            float af[TM], bf[TN];
            #pragma unroll
            for (int i = 0; i < TM; i += 4) {
                float4 t = *(const float4*)&As[buf][kk][ty * TM + i];
                af[i] = t.x; af[i + 1] = t.y; af[i + 2] = t.z; af[i + 3] = t.w;
            }
            #pragma unroll
            for (int j = 0; j < TN; j += 4) {
                float4 t = *(const float4*)&Bs[buf][kk][tx * TN + j];
                bf[j] = t.x; bf[j + 1] = t.y; bf[j + 2] = t.z; bf[j + 3] = t.w;
            }
            #pragma unroll
            for (int i = 0; i < TM; ++i)
                #pragma unroll
                for (int j = 0; j < TN; ++j)
                    acc[i][j] = fmaf(af[i], bf[j], acc[i][j]);
        }
        if (kb + 1 < nk) {
            const int nb = buf ^ 1;
            As[nb][acol + 0][arow] = av.x; As[nb][acol + 1][arow] = av.y;
            As[nb][acol + 2][arow] = av.z; As[nb][acol + 3][arow] = av.w;
            if (TRANSB) {
                Bs[nb][acol + 0][arow] = bv.x; Bs[nb][acol + 1][arow] = bv.y;
                Bs[nb][acol + 2][arow] = bv.z; Bs[nb][acol + 3][arow] = bv.w;
            } else {
                *(float4*)&Bs[nb][brow][bcol] = bv;
            }
            __syncthreads();
            buf = nb;
        }
    }

    // ---------------- Epilogues ----------------
    if (EPI == EPI_STORE || EPI == EPI_SCALE) {
        #pragma unroll
        for (int i = 0; i < TM; ++i) {
            float* crow = C + (size_t)(m0 + ty * TM + i) * ldc + n0 + tx * TN;
            #pragma unroll
            for (int j = 0; j < TN; j += 4) {
                float4 o;
                o.x = acc[i][j + 0] * scale; o.y = acc[i][j + 1] * scale;
                o.z = acc[i][j + 2] * scale; o.w = acc[i][j + 3] * scale;
                *(float4*)&crow[j] = o;
            }
        }
    } else if (EPI == EPI_QKV) {
        // route columns of qkv into u_q / u_k / v (n0 aligned to 128 <= 1024)
        float* dst; int nbase;
        if (n0 < DD)            { dst = g_u[0]; nbase = n0; }
        else if (n0 < 2 * DD)   { dst = g_u[1]; nbase = n0 - DD; }
        else                    { dst = g_vv;   nbase = n0 - 2 * DD; }
        #pragma unroll
        for (int i = 0; i < TM; ++i) {
            float* crow = dst + (size_t)(m0 + ty * TM + i) * DD + nbase + tx * TN;
            #pragma unroll
            for (int j = 0; j < TN; j += 4) {
                float4 o;
                o.x = acc[i][j + 0]; o.y = acc[i][j + 1];
                o.z = acc[i][j + 2]; o.w = acc[i][j + 3];
                *(float4*)&crow[j] = o;
            }
        }
    } else { // EPI_LCA : v += eta*(u - v - aG);  a = soft(v, lam)
        const float lam = g_lam[zsel];
        float* vp = g_vst[zsel];
        const float* up = g_u[zsel];
        float* ap = g_a[pout][zsel];
        #pragma unroll
        for (int i = 0; i < TM; ++i) {
            const size_t base = (size_t)(m0 + ty * TM + i) * DD + n0 + tx * TN;
            #pragma unroll
            for (int j = 0; j < TN; j += 4) {
                float4 uu = *(const float4*)&up[base + j];
                float4 vv = *(const float4*)&vp[base + j];
                float4 vn, an;
                vn.x = vv.x + ETA * (uu.x - vv.x - acc[i][j + 0]);
                vn.y = vv.y + ETA * (uu.y - vv.y - acc[i][j + 1]);
                vn.z = vv.z + ETA * (uu.z - vv.z - acc[i][j + 2]);
                vn.w = vv.w + ETA * (uu.w - vv.w - acc[i][j + 3]);
                an.x = softthr(vn.x, lam); an.y = softthr(vn.y, lam);
                an.z = softthr(vn.z, lam); an.w = softthr(vn.w, lam);
                *(float4*)&vp[base + j] = vn;
                *(float4*)&ap[base + j] = an;
            }
        }
    }
}

// ------------------------------------------------------------------
// Kernels
// ------------------------------------------------------------------
__global__ void k_prep(const float* __restrict__ Gq, const float* __restrict__ Gk,
                       const float* __restrict__ llq, const float* __restrict__ llk) {
    const size_t gid = (size_t)blockIdx.x * NTHREADS + threadIdx.x;
    if (gid == 0) { g_lam[0] = expf(llq[0]); g_lam[1] = expf(llk[0]); }
    const int z = (int)(gid >> 20);              // D*D = 2^20
    const int rc = (int)(gid & (DD * DD - 1));
    const int r = rc >> 10, c = rc & (DD - 1);
    const float* Gr = z ? Gk : Gq;
    g_G[z][rc] = (r == c) ? 0.f : 0.5f * (Gr[rc] + Gr[(size_t)c * DD + r]);
}

__global__ void k_qkv(const float* __restrict__ x, const float* __restrict__ W) {
    gemm_core<true, EPI_QKV>(x, W, nullptr, DD, DD, 0, DD, 1.f, 0, 0);
}

// LCA iteration 1 (a=0, v=0): v = eta*u, a = soft(v)
__global__ void k_lca_init() {
    const int z = blockIdx.z;
    const float lam = g_lam[z];
    const size_t i = (size_t)blockIdx.x * NTHREADS + threadIdx.x;
    float4 u = ((const float4*)g_u[z])[i];
    float4 v, a;
    v.x = ETA * u.x; v.y = ETA * u.y; v.z = ETA * u.z; v.w = ETA * u.w;
    a.x = softthr(v.x, lam); a.y = softthr(v.y, lam);
    a.z = softthr(v.z, lam); a.w = softthr(v.w, lam);
    ((float4*)g_vst[z])[i] = v;
    ((float4*)g_a[0][z])[i] = a;
}

__global__ void k_lca_gemm(int pin) {
    const int z = blockIdx.z;
    gemm_core<true, EPI_LCA>(g_a[pin][z], g_G[z], nullptr,
                             DD, DD, 0, DD, 1.f, z, pin ^ 1);
}

__global__ void k_scores() {
    if (blockIdx.x > blockIdx.y) return;   // block fully above causal diagonal
    const int b = blockIdx.z;
    gemm_core<true, EPI_SCALE>(g_a[1][0] + (size_t)b * TT * DD,
                               g_a[1][1] + (size_t)b * TT * DD,
                               g_scores + (size_t)b * TT * TT,
                               DD, DD, TT, DD, 0.03125f /*1/sqrt(1024)*/, 0, 0);
}

__global__ void k_softmax() {
    const int i = blockIdx.x, b = blockIdx.y, tid = threadIdx.x;
    float* s = g_scores + ((size_t)b * TT + i) * TT;
    const int len = i + 1;
    __shared__ float red[NTHREADS];

    float mx = -3.4e38f;
    for (int j = tid; j < len; j += NTHREADS) mx = fmaxf(mx, s[j]);
    red[tid] = mx; __syncthreads();
    for (int st = NTHREADS / 2; st > 0; st >>= 1) {
        if (tid < st) red[tid] = fmaxf(red[tid], red[tid + st]);
        __syncthreads();
    }
    mx = red[0]; __syncthreads();

    float sum = 0.f;
    for (int j = tid; j < len; j += NTHREADS) {
        float e = __expf(s[j] - mx);
        s[j] = e;
        sum += e;
    }
    red[tid] = sum; __syncthreads();
    for (int st = NTHREADS / 2; st > 0; st >>= 1) {
        if (tid < st) red[tid] += red[tid + st];
        __syncthreads();
    }
    const float inv = 1.f / red[0];

    for (int j = tid; j < len; j += NTHREADS) s[j] *= inv;
    for (int j = len + tid; j < TT; j += NTHREADS) s[j] = 0.f;  // zero masked cols
}

__global__ void k_av() {
    const int b = blockIdx.z;
    const int kEnd = (blockIdx.y + 1) * BM;   // causal: p[i,j]=0 for j>i
    gemm_core<false, EPI_STORE>(g_scores + (size_t)b * TT * TT,
                                g_vv + (size_t)b * TT * DD,
                                g_att + (size_t)b * TT * DD,
                                TT, DD, DD, kEnd, 1.f, 0, 0);
}

__global__ void k_out(const float* __restrict__ W, float* __restrict__ out) {
    gemm_core<true, EPI_STORE>(g_att, W, out, DD, DD, DD, DD, 1.f, 0, 0);
}

// ------------------------------------------------------------------
// Launch (graph-capturable: kernels only, default stream)
// ------------------------------------------------------------------
extern "C" void kernel_launch(void* const* d_in, const int* in_sizes, int n_in,
                              void* d_out, int out_size) {
    const float* x    = (const float*)d_in[0];  // [4,2048,1024]
    const float* Wqkv = (const float*)d_in[1];  // [3072,1024]
    const float* Wout = (const float*)d_in[2];  // [1024,1024]
    const float* Gq   = (const float*)d_in[3];  // [1024,1024]
    const float* llq  = (const float*)d_in[4];  // scalar
    const float* Gk   = (const float*)d_in[5];  // [1024,1024]
    const float* llk  = (const float*)d_in[6];  // scalar
    float* out = (float*)d_out;                 // [4,2048,1024]

    // G symmetrize + zero diag, lam = exp(log_lam)
    k_prep<<<2 * DD * DD / NTHREADS, NTHREADS>>>(Gq, Gk, llq, llk);

    // qkv projection, columns routed to u_q / u_k / v
    k_qkv<<<dim3(3 * DD / BN, MR / BM), NTHREADS>>>(x, Wqkv);

    // LCA iteration 1 (elementwise), then 9 GEMM iterations for q and k (z-dim)
    k_lca_init<<<dim3(MR * DD / 4 / NTHREADS, 1, 2), NTHREADS>>>();
    for (int it = 0; it < 9; ++it)
        k_lca_gemm<<<dim3(DD / BN, MR / BM, 2), NTHREADS>>>(it & 1);

    // attention
    k_scores<<<dim3(TT / BN, TT / BM, BB), NTHREADS>>>();
    k_softmax<<<dim3(TT, BB), NTHREADS>>>();
    k_av<<<dim3(DD / BN, TT / BM, BB), NTHREADS>>>();

    // output projection
    k_out<<<dim3(DD / BN, MR / BM), NTHREADS>>>(Wout, out);
}